// round 1
// baseline (speedup 1.0000x reference)
#include <cuda_runtime.h>
#include <cuda_bf16.h>
#include <math.h>

// Problem geometry (fixed by the dataset reference)
#define NB 8
#define LL 4096
#define HH 8
#define DD 64
#define HT 64
#define WD 64
#define NHH (NB*HH)          // 64
#define CHUNKS 16
#define CROWS (LL/CHUNKS)    // 256
#define ROWSTRIDE (HH*DD)    // 512
#define TILE_L 128
#define TY 16

typedef unsigned long long ull;

// ---------------- device scratch (static, allocation-free) ----------------
__device__ float g_inv_scale[DD];
__device__ float g_kvp[CHUNKS][NHH][DD][DD];   // 16 MB partial kv
__device__ float g_ksp[CHUNKS][NHH][DD];       // partial ksum
__device__ float g_kv[NHH][DD][DD];
__device__ float g_ksum[NHH][DD];

// ---------------- f32x2 helpers (FFMA2: 2x fp32 throughput) ----------------
__device__ __forceinline__ void ffma2(ull& d, ull a, ull b){
    asm("fma.rn.f32x2 %0, %1, %2, %0;" : "+l"(d) : "l"(a), "l"(b));
}
__device__ __forceinline__ ull pack2(float lo, float hi){
    ull r; asm("mov.b64 %0, {%1, %2};" : "=l"(r) : "f"(lo), "f"(hi)); return r;
}
__device__ __forceinline__ void unpack2(ull v, float& lo, float& hi){
    asm("mov.b64 {%0, %1}, %2;" : "=f"(lo), "=f"(hi) : "l"(v));
}
__device__ __forceinline__ void fadd2(ull& d, ull a){
    asm("add.rn.f32x2 %0, %0, %1;" : "+l"(d) : "l"(a));
}
__device__ __forceinline__ void f4add(float4& a, const float4 b){
    a.x += b.x; a.y += b.y; a.z += b.z; a.w += b.w;
}

// ---------------- K0: inv softplus scale ----------------
__global__ void k_init(const float* __restrict__ sp){
    int t = threadIdx.x;
    if (t < DD){
        float p = sp[t];
        float s = (p > 20.f) ? p : log1pf(expf(p));
        g_inv_scale[t] = 1.f / s;
    }
}

// ---------------- K1: kv & ksum partials per (nh, chunk) ----------------
// 128 threads. Thread owns d = {dh, dh+32} x 16 j-cols (as 8 f32x2 pairs each).
__global__ void __launch_bounds__(128) k_kv(const float* __restrict__ keys,
                                            const float* __restrict__ values){
    const int nh    = blockIdx.x & (NHH-1);
    const int chunk = blockIdx.x >> 6;
    const int n = nh >> 3, h = nh & 7;
    const int t = threadIdx.x, w = t >> 5, l = t & 31;
    const int dh = t >> 2, jq = t & 3;

    __shared__ float ks[4][DD];
    __shared__ float vs[4][DD];
    __shared__ float ksum_sh[4][DD];

    const float inv0 = g_inv_scale[l], inv1 = g_inv_scale[l+32];
    const size_t base = ((size_t)(n*LL + chunk*CROWS)*HH + h)*DD;

    ull acc0[8], acc1[8];
    #pragma unroll
    for (int p = 0; p < 8; ++p){ acc0[p] = 0ull; acc1[p] = 0ull; }
    float ksa0 = 0.f, ksa1 = 0.f;

    for (int it = 0; it < CROWS/4; ++it){
        const int r = it*4 + w;
        const float* kp = keys   + base + (size_t)r*ROWSTRIDE;
        const float* vp = values + base + (size_t)r*ROWSTRIDE;
        // focused transform of k row (warp-per-row, lane owns d=l, l+32)
        float x0 = (fmaxf(kp[l],    0.f) + 1e-6f) * inv0;
        float x1 = (fmaxf(kp[l+32], 0.f) + 1e-6f) * inv1;
        float v0 = vp[l], v1 = vp[l+32];
        float c0 = x0*x0*x0, c1 = x1*x1*x1;
        float s2 = x0*x0 + x1*x1;
        float s6 = c0*c0 + c1*c1;
        #pragma unroll
        for (int o = 16; o; o >>= 1){
            s2 += __shfl_xor_sync(0xffffffffu, s2, o);
            s6 += __shfl_xor_sync(0xffffffffu, s6, o);
        }
        const float rt = sqrtf(s2 / s6);
        x0 = c0*rt; x1 = c1*rt;

        __syncthreads();                 // previous iteration fully consumed
        ks[w][l] = x0; ks[w][l+32] = x1;
        vs[w][l] = v0; vs[w][l+32] = v1;
        __syncthreads();
        ksa0 += x0; ksa1 += x1;

        #pragma unroll
        for (int r2 = 0; r2 < 4; ++r2){
            const float kd0 = ks[r2][dh], kd1 = ks[r2][dh+32];
            const ull k0 = pack2(kd0, kd0), k1 = pack2(kd1, kd1);
            const ulonglong2* vvp = (const ulonglong2*)&vs[r2][jq*16];
            #pragma unroll
            for (int q2 = 0; q2 < 4; ++q2){
                ulonglong2 vv = vvp[q2];
                ffma2(acc0[q2*2+0], k0, vv.x);
                ffma2(acc0[q2*2+1], k0, vv.y);
                ffma2(acc1[q2*2+0], k1, vv.x);
                ffma2(acc1[q2*2+1], k1, vv.y);
            }
        }
    }

    ksum_sh[w][l] = ksa0; ksum_sh[w][l+32] = ksa1;
    __syncthreads();

    ull* o0 = (ull*)&g_kvp[chunk][nh][dh]   [jq*16];
    ull* o1 = (ull*)&g_kvp[chunk][nh][dh+32][jq*16];
    #pragma unroll
    for (int p = 0; p < 8; ++p){ o0[p] = acc0[p]; o1[p] = acc1[p]; }
    if (t < DD){
        float s = ksum_sh[0][t] + ksum_sh[1][t] + ksum_sh[2][t] + ksum_sh[3][t];
        g_ksp[chunk][nh][t] = s;
    }
}

// ---------------- K1b: deterministic chunk reduction ----------------
__global__ void __launch_bounds__(256) k_kvreduce(){
    const int nh = blockIdx.x;
    const int t  = threadIdx.x;
    float4 s0 = make_float4(0,0,0,0), s1 = s0, s2 = s0, s3 = s0;
    #pragma unroll
    for (int c = 0; c < CHUNKS; ++c){
        const float4* p = (const float4*)&g_kvp[c][nh][0][0] + (size_t)t*4;
        f4add(s0, p[0]); f4add(s1, p[1]); f4add(s2, p[2]); f4add(s3, p[3]);
    }
    float4* o = (float4*)&g_kv[nh][0][0] + (size_t)t*4;
    o[0] = s0; o[1] = s1; o[2] = s2; o[3] = s3;
    if (t < DD){
        float s = 0.f;
        #pragma unroll
        for (int c = 0; c < CHUNKS; ++c) s += g_ksp[c][nh][t];
        g_ksum[nh][t] = s;
    }
}

// ---------------- K2: attention output GEMM ----------------
// Dynamic smem: kv_s[64*64] | ksum_s[64] | qt[64][132] (z folded, transposed, padded)
#define K2_SMEM_FLOATS (4096 + 64 + 64*132)
__global__ void __launch_bounds__(256) k_attn(const float* __restrict__ qin,
                                              float* __restrict__ out){
    extern __shared__ float sm[];
    float* kv_s   = sm;
    float* ksum_s = sm + 4096;
    float* qt     = sm + 4160;

    const int nh = blockIdx.x & (NHH-1);
    const int lt = blockIdx.x >> 6;
    const int n = nh >> 3, h = nh & 7;
    const int t = threadIdx.x, w = t >> 5, l = t & 31;

    {
        const float4* src = (const float4*)&g_kv[nh][0][0];
        float4* dst = (float4*)kv_s;
        #pragma unroll
        for (int i = 0; i < 4; ++i) dst[t + i*256] = src[t + i*256];
        if (t < DD) ksum_s[t] = g_ksum[nh][t];
    }
    __syncthreads();

    const float inv0 = g_inv_scale[l], inv1 = g_inv_scale[l+32];
    const float ks0 = ksum_s[l], ks1 = ksum_s[l+32];
    const size_t base = ((size_t)(n*LL + lt*TILE_L)*HH + h)*DD;

    // transform 128 q rows; store q' * (r * z) transposed into qt[d][row]
    for (int rr = 0; rr < TILE_L/8; ++rr){
        const int row = rr*8 + w;
        const float* qp = qin + base + (size_t)row*ROWSTRIDE;
        float x0 = (fmaxf(qp[l],    0.f) + 1e-6f) * inv0;
        float x1 = (fmaxf(qp[l+32], 0.f) + 1e-6f) * inv1;
        float c0 = x0*x0*x0, c1 = x1*x1*x1;
        float s2 = x0*x0 + x1*x1;
        float s6 = c0*c0 + c1*c1;
        float sd = c0*ks0 + c1*ks1;
        #pragma unroll
        for (int o = 16; o; o >>= 1){
            s2 += __shfl_xor_sync(0xffffffffu, s2, o);
            s6 += __shfl_xor_sync(0xffffffffu, s6, o);
            sd += __shfl_xor_sync(0xffffffffu, sd, o);
        }
        const float rt = sqrtf(s2 / s6);
        const float z  = 1.f / (rt*sd + 1e-6f);
        const float m  = rt * z;
        qt[l*132 + row]      = c0 * m;
        qt[(l+32)*132 + row] = c1 * m;
    }
    __syncthreads();

    // register-tiled GEMM: thread = 8 rows (4 f32x2 pairs) x 4 cols
    const int tr = t >> 4, tc = t & 15;
    ull acc[4][4];
    #pragma unroll
    for (int p = 0; p < 4; ++p)
        #pragma unroll
        for (int c = 0; c < 4; ++c) acc[p][c] = 0ull;

    const float* kvcol = kv_s + tc*4;
    #pragma unroll 8
    for (int d = 0; d < DD; ++d){
        const ulonglong2* ap = (const ulonglong2*)&qt[d*132 + tr*8];
        ulonglong2 a01 = ap[0], a23 = ap[1];
        const float4 b = *(const float4*)(kvcol + d*DD);
        const ull b0 = pack2(b.x, b.x), b1 = pack2(b.y, b.y);
        const ull b2 = pack2(b.z, b.z), b3 = pack2(b.w, b.w);
        ffma2(acc[0][0], a01.x, b0); ffma2(acc[0][1], a01.x, b1);
        ffma2(acc[0][2], a01.x, b2); ffma2(acc[0][3], a01.x, b3);
        ffma2(acc[1][0], a01.y, b0); ffma2(acc[1][1], a01.y, b1);
        ffma2(acc[1][2], a01.y, b2); ffma2(acc[1][3], a01.y, b3);
        ffma2(acc[2][0], a23.x, b0); ffma2(acc[2][1], a23.x, b1);
        ffma2(acc[2][2], a23.x, b2); ffma2(acc[2][3], a23.x, b3);
        ffma2(acc[3][0], a23.y, b0); ffma2(acc[3][1], a23.y, b1);
        ffma2(acc[3][2], a23.y, b2); ffma2(acc[3][3], a23.y, b3);
    }

    float* ob = out + base + (size_t)(tr*8)*ROWSTRIDE + tc*4;
    #pragma unroll
    for (int p = 0; p < 4; ++p){
        float4 lo, hi;
        unpack2(acc[p][0], lo.x, hi.x);
        unpack2(acc[p][1], lo.y, hi.y);
        unpack2(acc[p][2], lo.z, hi.z);
        unpack2(acc[p][3], lo.w, hi.w);
        *(float4*)(ob + (size_t)(2*p  )*ROWSTRIDE) = lo;
        *(float4*)(ob + (size_t)(2*p+1)*ROWSTRIDE) = hi;
    }
}

// ---------------- K3: depthwise 5x5 conv, out += conv(v) + bias ----------------
// Dynamic smem: ring[5][68][64] | wsh[25][64]
#define K3_SMEM_FLOATS (5*68*64 + 25*64)
__global__ void __launch_bounds__(256,2) k_conv(const float* __restrict__ vin,
                                                const float* __restrict__ wt,
                                                const float* __restrict__ bias,
                                                float* __restrict__ out){
    extern __shared__ float sm[];
    float* ring = sm;                 // 5*68*64
    float* wsh  = sm + 5*68*64;       // 25*64

    const int yt = blockIdx.x & 3;
    const int nh = blockIdx.x >> 2;
    const int n = nh >> 3, h = nh & 7;
    const int t = threadIdx.x;
    const int dp = t & 31;            // d pair: d = 2*dp
    const int xg = t >> 5;            // x group 0..7

    for (int i = t; i < 25*DD; i += 256){
        int tap = i >> 6, d = i & 63;
        wsh[i] = wt[d*25 + tap];      // wsh[tap][d]
    }
    {   // zero x-pads (xp = 0,1,66,67) once; row loads never touch them
        int xi = t >> 6;
        int d  = t & 63;
        int xp = (xi < 2) ? xi : (64 + xi);
        #pragma unroll
        for (int s = 0; s < 5; ++s) ring[(s*68 + xp)*64 + d] = 0.f;
    }
    __syncthreads();

    ull wr[25];
    #pragma unroll
    for (int i = 0; i < 25; ++i) wr[i] = *(const ull*)&wsh[i*64 + 2*dp];
    const ull bias2 = *(const ull*)(bias + 2*dp);

    const int y0 = yt*TY;

    auto loadrow = [&](int y){
        const int s = (y + 10) % 5;
        float* dst = ring + (size_t)s*68*64;
        if (y < 0 || y >= HT){
            #pragma unroll
            for (int k2 = 0; k2 < 4; ++k2){
                int f = t + k2*256;             // float4 index
                int x = f >> 4, dq = f & 15;
                *(float4*)&dst[(x+2)*64 + dq*4] = make_float4(0.f,0.f,0.f,0.f);
            }
        } else {
            const float* src = vin + ((size_t)(n*LL + y*WD)*HH + h)*DD;
            #pragma unroll
            for (int k2 = 0; k2 < 4; ++k2){
                int f = t + k2*256;
                int x = f >> 4, dq = f & 15;
                *(float4*)&dst[(x+2)*64 + dq*4] =
                    *(const float4*)&src[(size_t)x*ROWSTRIDE + dq*4];
            }
        }
    };

    loadrow(y0-2); loadrow(y0-1); loadrow(y0); loadrow(y0+1);

    for (int yo = 0; yo < TY; ++yo){
        const int y = y0 + yo;
        loadrow(y+2);
        __syncthreads();

        ull acc[8];
        #pragma unroll
        for (int xx = 0; xx < 8; ++xx) acc[xx] = bias2;
        const int x0 = xg*8;

        #pragma unroll
        for (int dy = 0; dy < 5; ++dy){
            const int s = (y + dy + 8) % 5;     // slot of row y+dy-2
            const float* rp = ring + (size_t)s*68*64 + 2*dp;
            ull win[12];
            #pragma unroll
            for (int i = 0; i < 12; ++i) win[i] = *(const ull*)&rp[(x0+i)*64];
            #pragma unroll
            for (int xx = 0; xx < 8; ++xx)
                #pragma unroll
                for (int dx = 0; dx < 5; ++dx)
                    ffma2(acc[xx], wr[dy*5+dx], win[xx+dx]);
        }

        float* ob = out + ((size_t)(n*LL + y*WD + x0)*HH + h)*DD + 2*dp;
        #pragma unroll
        for (int xx = 0; xx < 8; ++xx){
            ull o = *(const ull*)(ob + (size_t)xx*ROWSTRIDE);
            fadd2(acc[xx], o);
            *(ull*)(ob + (size_t)xx*ROWSTRIDE) = acc[xx];
        }
        __syncthreads();
    }
}

// ---------------- launch ----------------
extern "C" void kernel_launch(void* const* d_in, const int* in_sizes, int n_in,
                              void* d_out, int out_size){
    const float* q  = (const float*)d_in[0];
    const float* k  = (const float*)d_in[1];
    const float* v  = (const float*)d_in[2];
    const float* sp = (const float*)d_in[3];
    const float* w  = (const float*)d_in[4];
    const float* b  = (const float*)d_in[5];
    float* out = (float*)d_out;

    cudaFuncSetAttribute(k_attn, cudaFuncAttributeMaxDynamicSharedMemorySize,
                         K2_SMEM_FLOATS*4);
    cudaFuncSetAttribute(k_conv, cudaFuncAttributeMaxDynamicSharedMemorySize,
                         K3_SMEM_FLOATS*4);

    k_init<<<1, 64>>>(sp);
    k_kv<<<NHH*CHUNKS, 128>>>(k, v);
    k_kvreduce<<<NHH, 256>>>();
    k_attn<<<NHH*(LL/TILE_L), 256, K2_SMEM_FLOATS*4>>>(q, out);
    k_conv<<<NHH*(HT/TY), 256, K3_SMEM_FLOATS*4>>>(v, w, b, out);
}

// round 2
// speedup vs baseline: 1.4104x; 1.4104x over previous
#include <cuda_runtime.h>
#include <cuda_bf16.h>
#include <math.h>

#define NB 8
#define LL 4096
#define HH 8
#define DD 64
#define HT 64
#define WD 64
#define NHH (NB*HH)          // 64
#define CHUNKS 16
#define CROWS (LL/CHUNKS)    // 256
#define ROWSTRIDE (HH*DD)    // 512
#define TILE_L 128
#define TY 16

typedef unsigned long long ull;

// ---------------- device scratch ----------------
__device__ float g_inv_scale[DD];
__device__ float g_kvp[CHUNKS][NHH][DD][DD];
__device__ float g_ksp[CHUNKS][NHH][DD];
__device__ float g_kv[NHH][DD][DD];
__device__ float g_ksum[NHH][DD];

// ---------------- f32x2 helpers ----------------
__device__ __forceinline__ void ffma2(ull& d, ull a, ull b){
    asm("fma.rn.f32x2 %0, %1, %2, %0;" : "+l"(d) : "l"(a), "l"(b));
}
__device__ __forceinline__ ull pack2(float lo, float hi){
    ull r; asm("mov.b64 %0, {%1, %2};" : "=l"(r) : "f"(lo), "f"(hi)); return r;
}
__device__ __forceinline__ void fadd2(ull& d, ull a){
    asm("add.rn.f32x2 %0, %0, %1;" : "+l"(d) : "l"(a));
}
__device__ __forceinline__ void f4add(float4& a, const float4 b){
    a.x += b.x; a.y += b.y; a.z += b.z; a.w += b.w;
}

// ---------------- K0: inv softplus scale ----------------
__global__ void k_init(const float* __restrict__ sp){
    int t = threadIdx.x;
    if (t < DD){
        float p = sp[t];
        float s = (p > 20.f) ? p : log1pf(expf(p));
        g_inv_scale[t] = 1.f / s;
    }
}

// ---------------- K1: kv partials — smem-tiled GEMM ----------------
// 64 threads/block. One (chunk, nh). Stages of 64 rows; XOR-swizzled tiles.
// Thread = 8 d-rows x 8 j-cols (as 8x4 f32x2 accumulators).
__global__ void __launch_bounds__(64) k_kv(const float* __restrict__ keys,
                                           const float* __restrict__ values){
    __shared__ float4 kt4[64*16];
    __shared__ float4 vt4[64*16];
    __shared__ float4 inv4s[16];

    const int nh    = blockIdx.x & (NHH-1);
    const int chunk = blockIdx.x >> 6;
    const int n = nh >> 3, h = nh & 7;
    const int t = threadIdx.x;
    const int td = t >> 3, tj = t & 7;
    if (t < 16) inv4s[t] = ((const float4*)g_inv_scale)[t];

    const size_t base = ((size_t)(n*LL + chunk*CROWS)*HH + h)*DD;

    ull acc[8][4];
    #pragma unroll
    for (int a = 0; a < 8; ++a)
        #pragma unroll
        for (int b = 0; b < 4; ++b) acc[a][b] = 0ull;
    float4 ksA = make_float4(0,0,0,0), ksB = make_float4(0,0,0,0);

    for (int stage = 0; stage < CROWS/64; ++stage){
        __syncthreads();
        // thread-per-row transform of k, stage k' and v into swizzled tiles
        const int r = stage*64 + t;
        const float4* kp = (const float4*)(keys   + base + (size_t)r*ROWSTRIDE);
        const float4* vp = (const float4*)(values + base + (size_t)r*ROWSTRIDE);
        float4 c[16];
        float s2 = 0.f, s6 = 0.f;
        #pragma unroll
        for (int i = 0; i < 16; ++i){
            float4 k4 = kp[i], iv = inv4s[i], x, cc;
            x.x = (fmaxf(k4.x,0.f)+1e-6f)*iv.x;
            x.y = (fmaxf(k4.y,0.f)+1e-6f)*iv.y;
            x.z = (fmaxf(k4.z,0.f)+1e-6f)*iv.z;
            x.w = (fmaxf(k4.w,0.f)+1e-6f)*iv.w;
            cc.x = x.x*x.x*x.x; cc.y = x.y*x.y*x.y;
            cc.z = x.z*x.z*x.z; cc.w = x.w*x.w*x.w;
            s2 += x.x*x.x + x.y*x.y + x.z*x.z + x.w*x.w;
            s6 += cc.x*cc.x + cc.y*cc.y + cc.z*cc.z + cc.w*cc.w;
            c[i] = cc;
        }
        const float rt = sqrtf(s2/s6);
        const int swb = t & 15;
        #pragma unroll
        for (int i = 0; i < 16; ++i){
            float4 cc = c[i];
            cc.x *= rt; cc.y *= rt; cc.z *= rt; cc.w *= rt;
            kt4[t*16 + (i ^ swb)] = cc;
            vt4[t*16 + (i ^ swb)] = vp[i];
        }
        __syncthreads();

        #pragma unroll 4
        for (int r2 = 0; r2 < 64; ++r2){
            const int sw = r2 & 15;
            const float4 a0 = kt4[r2*16 + ((td*2  ) ^ sw)];
            const float4 a1 = kt4[r2*16 + ((td*2+1) ^ sw)];
            const ulonglong2 b0 = *(const ulonglong2*)&vt4[r2*16 + ((tj*2  ) ^ sw)];
            const ulonglong2 b1 = *(const ulonglong2*)&vt4[r2*16 + ((tj*2+1) ^ sw)];
            if (tj == 0){ f4add(ksA, a0); f4add(ksB, a1); }
            const float ka[8] = {a0.x,a0.y,a0.z,a0.w,a1.x,a1.y,a1.z,a1.w};
            #pragma unroll
            for (int dd = 0; dd < 8; ++dd){
                const ull k2 = pack2(ka[dd], ka[dd]);
                ffma2(acc[dd][0], k2, b0.x);
                ffma2(acc[dd][1], k2, b0.y);
                ffma2(acc[dd][2], k2, b1.x);
                ffma2(acc[dd][3], k2, b1.y);
            }
        }
    }

    #pragma unroll
    for (int dd = 0; dd < 8; ++dd){
        ull* o = (ull*)&g_kvp[chunk][nh][td*8+dd][tj*8];
        o[0]=acc[dd][0]; o[1]=acc[dd][1]; o[2]=acc[dd][2]; o[3]=acc[dd][3];
    }
    if (tj == 0){
        ((float4*)&g_ksp[chunk][nh][td*8])[0] = ksA;
        ((float4*)&g_ksp[chunk][nh][td*8])[1] = ksB;
    }
}

// ---------------- K1b: deterministic chunk reduction ----------------
__global__ void __launch_bounds__(256) k_kvreduce(){
    const int nh = blockIdx.x;
    const int t  = threadIdx.x;
    float4 s0 = make_float4(0,0,0,0), s1 = s0, s2 = s0, s3 = s0;
    #pragma unroll
    for (int c = 0; c < CHUNKS; ++c){
        const float4* p = (const float4*)&g_kvp[c][nh][0][0] + (size_t)t*4;
        f4add(s0, p[0]); f4add(s1, p[1]); f4add(s2, p[2]); f4add(s3, p[3]);
    }
    float4* o = (float4*)&g_kv[nh][0][0] + (size_t)t*4;
    o[0] = s0; o[1] = s1; o[2] = s2; o[3] = s3;
    if (t < DD){
        float s = 0.f;
        #pragma unroll
        for (int c = 0; c < CHUNKS; ++c) s += g_ksp[c][nh][t];
        g_ksum[nh][t] = s;
    }
}

// ---------------- K2: attention GEMM (RMW add onto conv output) ----------------
// 128 threads, tile 128 rows. Thread-per-row transform, 8x8 GEMM tile.
#define K2_SMEM_FLOATS (4096 + 64 + 64 + 64*132)
__global__ void __launch_bounds__(128) k_attn(const float* __restrict__ qin,
                                              float* __restrict__ out){
    extern __shared__ float sm[];
    float* kv_s   = sm;            // 4096
    float* ksum_s = sm + 4096;     // 64
    float* inv_s  = sm + 4160;     // 64
    float* qt     = sm + 4224;     // 64 x 132

    const int nh = blockIdx.x & (NHH-1);
    const int lt = blockIdx.x >> 6;
    const int n = nh >> 3, h = nh & 7;
    const int t = threadIdx.x;

    {
        const float4* src = (const float4*)&g_kv[nh][0][0];
        float4* dst = (float4*)kv_s;
        #pragma unroll
        for (int i = 0; i < 8; ++i) dst[t + i*128] = src[t + i*128];
        if (t < 16){
            ((float4*)ksum_s)[t] = ((const float4*)&g_ksum[nh][0])[t];
            ((float4*)inv_s )[t] = ((const float4*)g_inv_scale)[t];
        }
    }
    __syncthreads();

    const size_t base = ((size_t)(n*LL + lt*TILE_L)*HH + h)*DD;

    // transform row t: q' with z folded, stored transposed qt[d][row]
    {
        const float4* qp = (const float4*)(qin + base + (size_t)t*ROWSTRIDE);
        float4 c[16];
        float s2 = 0.f, s6 = 0.f, sd = 0.f;
        #pragma unroll
        for (int i = 0; i < 16; ++i){
            float4 q4 = qp[i];
            float4 iv = ((const float4*)inv_s)[i];
            float4 ks = ((const float4*)ksum_s)[i];
            float4 x, cc;
            x.x = (fmaxf(q4.x,0.f)+1e-6f)*iv.x;
            x.y = (fmaxf(q4.y,0.f)+1e-6f)*iv.y;
            x.z = (fmaxf(q4.z,0.f)+1e-6f)*iv.z;
            x.w = (fmaxf(q4.w,0.f)+1e-6f)*iv.w;
            cc.x = x.x*x.x*x.x; cc.y = x.y*x.y*x.y;
            cc.z = x.z*x.z*x.z; cc.w = x.w*x.w*x.w;
            s2 += x.x*x.x + x.y*x.y + x.z*x.z + x.w*x.w;
            s6 += cc.x*cc.x + cc.y*cc.y + cc.z*cc.z + cc.w*cc.w;
            sd += cc.x*ks.x + cc.y*ks.y + cc.z*ks.z + cc.w*ks.w;
            c[i] = cc;
        }
        const float rt = sqrtf(s2/s6);
        const float z  = 1.f / (rt*sd + 1e-6f);
        const float m  = rt * z;
        #pragma unroll
        for (int i = 0; i < 16; ++i){
            qt[(i*4+0)*132 + t] = c[i].x * m;
            qt[(i*4+1)*132 + t] = c[i].y * m;
            qt[(i*4+2)*132 + t] = c[i].z * m;
            qt[(i*4+3)*132 + t] = c[i].w * m;
        }
    }
    __syncthreads();

    // GEMM: thread = 8 rows x 8 cols (cols paired as f32x2)
    const int tr = t >> 3, tc = t & 7;
    ull acc[8][4];
    #pragma unroll
    for (int a = 0; a < 8; ++a)
        #pragma unroll
        for (int b = 0; b < 4; ++b) acc[a][b] = 0ull;

    #pragma unroll 4
    for (int d = 0; d < DD; ++d){
        const float4 a0 = *(const float4*)&qt[d*132 + tr*8];
        const float4 a1 = *(const float4*)&qt[d*132 + tr*8 + 4];
        const ulonglong2 b0 = *(const ulonglong2*)&kv_s[d*64 + tc*8];
        const ulonglong2 b1 = *(const ulonglong2*)&kv_s[d*64 + tc*8 + 4];
        const float aa[8] = {a0.x,a0.y,a0.z,a0.w,a1.x,a1.y,a1.z,a1.w};
        #pragma unroll
        for (int rr = 0; rr < 8; ++rr){
            const ull q2 = pack2(aa[rr], aa[rr]);
            ffma2(acc[rr][0], q2, b0.x);
            ffma2(acc[rr][1], q2, b0.y);
            ffma2(acc[rr][2], q2, b1.x);
            ffma2(acc[rr][3], q2, b1.y);
        }
    }

    // RMW epilogue: out already holds conv(v)+bias
    float* ob = out + base + (size_t)(tr*8)*ROWSTRIDE + tc*8;
    #pragma unroll
    for (int rr = 0; rr < 8; ++rr){
        ull* op = (ull*)(ob + (size_t)rr*ROWSTRIDE);
        ulonglong2 o0 = ((const ulonglong2*)op)[0];
        ulonglong2 o1 = ((const ulonglong2*)op)[1];
        fadd2(acc[rr][0], o0.x); fadd2(acc[rr][1], o0.y);
        fadd2(acc[rr][2], o1.x); fadd2(acc[rr][3], o1.y);
        ((ulonglong2*)op)[0] = make_ulonglong2(acc[rr][0], acc[rr][1]);
        ((ulonglong2*)op)[1] = make_ulonglong2(acc[rr][2], acc[rr][3]);
    }
}

// ---------------- K3: depthwise 5x5 conv, out = conv(v) + bias ----------------
#define K3_SMEM_FLOATS (5*68*64 + 25*64)
__global__ void __launch_bounds__(256,2) k_conv(const float* __restrict__ vin,
                                                const float* __restrict__ wt,
                                                const float* __restrict__ bias,
                                                float* __restrict__ out){
    extern __shared__ float sm[];
    float* ring = sm;                 // 5*68*64
    float* wsh  = sm + 5*68*64;       // 25*64

    const int yt = blockIdx.x & 3;
    const int nh = blockIdx.x >> 2;
    const int n = nh >> 3, h = nh & 7;
    const int t = threadIdx.x;
    const int dp = t & 31;
    const int xg = t >> 5;

    for (int i = t; i < 25*DD; i += 256){
        int tap = i >> 6, d = i & 63;
        wsh[i] = wt[d*25 + tap];
    }
    {
        int xi = t >> 6;
        int d  = t & 63;
        int xp = (xi < 2) ? xi : (64 + xi);
        #pragma unroll
        for (int s = 0; s < 5; ++s) ring[(s*68 + xp)*64 + d] = 0.f;
    }
    __syncthreads();

    ull wr[25];
    #pragma unroll
    for (int i = 0; i < 25; ++i) wr[i] = *(const ull*)&wsh[i*64 + 2*dp];
    const ull bias2 = *(const ull*)(bias + 2*dp);

    const int y0 = yt*TY;

    auto loadrow = [&](int y){
        const int s = (y + 10) % 5;
        float* dst = ring + (size_t)s*68*64;
        if (y < 0 || y >= HT){
            #pragma unroll
            for (int k2 = 0; k2 < 4; ++k2){
                int f = t + k2*256;
                int x = f >> 4, dq = f & 15;
                *(float4*)&dst[(x+2)*64 + dq*4] = make_float4(0.f,0.f,0.f,0.f);
            }
        } else {
            const float* src = vin + ((size_t)(n*LL + y*WD)*HH + h)*DD;
            #pragma unroll
            for (int k2 = 0; k2 < 4; ++k2){
                int f = t + k2*256;
                int x = f >> 4, dq = f & 15;
                *(float4*)&dst[(x+2)*64 + dq*4] =
                    *(const float4*)&src[(size_t)x*ROWSTRIDE + dq*4];
            }
        }
    };

    loadrow(y0-2); loadrow(y0-1); loadrow(y0); loadrow(y0+1);

    for (int yo = 0; yo < TY; ++yo){
        const int y = y0 + yo;
        loadrow(y+2);
        __syncthreads();

        ull acc[8];
        #pragma unroll
        for (int xx = 0; xx < 8; ++xx) acc[xx] = bias2;
        const int x0 = xg*8;

        #pragma unroll
        for (int dy = 0; dy < 5; ++dy){
            const int s = (y + dy + 8) % 5;
            const float* rp = ring + (size_t)s*68*64 + 2*dp;
            ull win[12];
            #pragma unroll
            for (int i = 0; i < 12; ++i) win[i] = *(const ull*)&rp[(x0+i)*64];
            #pragma unroll
            for (int xx = 0; xx < 8; ++xx)
                #pragma unroll
                for (int dx = 0; dx < 5; ++dx)
                    ffma2(acc[xx], wr[dy*5+dx], win[xx+dx]);
        }

        float* ob = out + ((size_t)(n*LL + y*WD + x0)*HH + h)*DD + 2*dp;
        #pragma unroll
        for (int xx = 0; xx < 8; ++xx)
            *(ull*)(ob + (size_t)xx*ROWSTRIDE) = acc[xx];
        __syncthreads();
    }
}

// ---------------- launch (fork-join: conv overlaps kv+reduce) ----------------
extern "C" void kernel_launch(void* const* d_in, const int* in_sizes, int n_in,
                              void* d_out, int out_size){
    const float* q  = (const float*)d_in[0];
    const float* k  = (const float*)d_in[1];
    const float* v  = (const float*)d_in[2];
    const float* sp = (const float*)d_in[3];
    const float* w  = (const float*)d_in[4];
    const float* b  = (const float*)d_in[5];
    float* out = (float*)d_out;

    static cudaStream_t s2 = nullptr;
    static cudaEvent_t evFork = nullptr, evJoin = nullptr;
    if (!s2){
        cudaStreamCreateWithFlags(&s2, cudaStreamNonBlocking);
        cudaEventCreateWithFlags(&evFork, cudaEventDisableTiming);
        cudaEventCreateWithFlags(&evJoin, cudaEventDisableTiming);
    }

    cudaFuncSetAttribute(k_attn, cudaFuncAttributeMaxDynamicSharedMemorySize,
                         K2_SMEM_FLOATS*4);
    cudaFuncSetAttribute(k_conv, cudaFuncAttributeMaxDynamicSharedMemorySize,
                         K3_SMEM_FLOATS*4);

    k_init<<<1, 64>>>(sp);

    // fork: conv (writes out = conv+bias) runs concurrently with kv pipeline
    cudaEventRecord(evFork, 0);
    cudaStreamWaitEvent(s2, evFork, 0);
    k_conv<<<NHH*(HT/TY), 256, K3_SMEM_FLOATS*4, s2>>>(v, w, b, out);
    cudaEventRecord(evJoin, s2);

    k_kv<<<NHH*CHUNKS, 64>>>(k, v);
    k_kvreduce<<<NHH, 256>>>();

    // join: attn RMW-adds attention onto conv output
    cudaStreamWaitEvent(0, evJoin, 0);
    k_attn<<<NHH*(LL/TILE_L), 256 - 128, K2_SMEM_FLOATS*4>>>(q, out);
}